// round 6
// baseline (speedup 1.0000x reference)
#include <cuda_runtime.h>
#include <cstdint>
#include <float.h>

// Problem shape (fixed by the dataset): P=512, R=256, S=256
#define RR 256
#define SS 256

// Stable top-3 insert: strict '>' + increasing scan order == jax.lax.top_k
// tie-breaking (earlier index wins on equal values). Tracks (value, index).
__device__ __forceinline__ void ins3i(float v, int i,
                                      float& a, int& ia,
                                      float& b, int& ib,
                                      float& c, int& ic) {
    bool ga = v > a, gb = v > b, gc = v > c;
    c  = gb ? b  : (gc ? v : c);
    ic = gb ? ib : (gc ? i : ic);
    b  = ga ? a  : (gb ? v : b);
    ib = ga ? ia : (gb ? i : ib);
    a  = ga ? v : a;
    ia = ga ? i : ia;
}

__device__ __forceinline__ void comp1(float v, bool fr, bool fc,
                                      bool rm, bool sm,
                                      float& so, float& co) {
    float e = __expf(v);
    so = 0.5f * ((fr ? e : 0.f) + (fc ? e : 0.f));
    co = ((fr || fc) && rm && sm) ? 1.f : 0.f;
}

__global__ __launch_bounds__(256, 4)
void iapm_kernel(const float* __restrict__ score,
                 const int* __restrict__ refm,    // bool masks stored as int32
                 const int* __restrict__ srcm,    // bool masks stored as int32
                 float* __restrict__ out,
                 long long n_total)      // P*R*S ; corr (f32) lives at out + n_total
{
    __shared__ int coli0[SS], coli1[SS], coli2[SS];   // top-3 row idx per column
    __shared__ int rowi0[RR], rowi1[RR], rowi2[RR];   // top-3 col idx per row
    __shared__ uint8_t rmask_sh[RR];
    __shared__ float tile[8][32][33];    // per-warp transpose tile, padded

    const int p = blockIdx.x;
    const int t = threadIdx.x;           // 0..255
    const int w = t >> 5;                // warp 0..7
    const int l = t & 31;                // lane
    const float* base = score + (size_t)p * (RR * SS);

    rmask_sh[t] = (refm[p * RR + t] != 0) ? 1 : 0;

    // ---- Phase 1: column top-3 (thread t owns column t; coalesced) ----
    {
        float a = -FLT_MAX, b = -FLT_MAX, c = -FLT_MAX;
        int ia = -1, ib = -1, ic = -1;
        #pragma unroll 8
        for (int r = 0; r < RR; r++) {
            ins3i(base[r * SS + t], r, a, ia, b, ib, c, ic);
        }
        coli0[t] = ia; coli1[t] = ib; coli2[t] = ic;
    }

    // ---- Phase 2: row top-3 via per-warp 32x32 SMEM transpose ----
    {
        float a = -FLT_MAX, b = -FLT_MAX, c = -FLT_MAX;
        int ia = -1, ib = -1, ic = -1;
        const int rb = w * 32;
        for (int cb = 0; cb < 8; cb++) {
            #pragma unroll
            for (int j = 0; j < 32; j++) {
                tile[w][j][l] = base[(rb + j) * SS + cb * 32 + l];
            }
            __syncwarp();
            #pragma unroll
            for (int j = 0; j < 32; j++) {
                ins3i(tile[w][l][j], cb * 32 + j, a, ia, b, ib, c, ic);
            }
            __syncwarp();
        }
        rowi0[rb + l] = ia; rowi1[rb + l] = ib; rowi2[rb + l] = ic;
    }
    __syncthreads();

    // ---- Phase 3: elementwise output, float4 in / float4 out ----
    {
        const int cg = t & 63;           // column group of 4
        const int r0 = t >> 6;           // 0..3 : row phase
        const int s0 = cg * 4;
        const int c0a = coli0[s0+0], c0b = coli1[s0+0], c0c = coli2[s0+0];
        const int c1a = coli0[s0+1], c1b = coli1[s0+1], c1c = coli2[s0+1];
        const int c2a = coli0[s0+2], c2b = coli1[s0+2], c2c = coli2[s0+2];
        const int c3a = coli0[s0+3], c3b = coli1[s0+3], c3c = coli2[s0+3];
        const int* smp = srcm + p * SS + s0;
        const bool sm0 = smp[0] != 0, sm1 = smp[1] != 0,
                   sm2 = smp[2] != 0, sm3 = smp[3] != 0;

        float* outs = out + (size_t)p * (RR * SS);
        float* outc = out + (size_t)n_total + (size_t)p * (RR * SS);

        #pragma unroll 4
        for (int j = 0; j < 64; j++) {
            const int r = j * 4 + r0;
            const int ra = rowi0[r], rb_ = rowi1[r], rc = rowi2[r];
            const bool rm = rmask_sh[r] != 0;
            const size_t off = (size_t)r * SS + s0;
            const float4 v4 = *reinterpret_cast<const float4*>(base + off);

            const bool fr0 = (s0+0 == ra) | (s0+0 == rb_) | (s0+0 == rc);
            const bool fr1 = (s0+1 == ra) | (s0+1 == rb_) | (s0+1 == rc);
            const bool fr2 = (s0+2 == ra) | (s0+2 == rb_) | (s0+2 == rc);
            const bool fr3 = (s0+3 == ra) | (s0+3 == rb_) | (s0+3 == rc);
            const bool fc0 = (r == c0a) | (r == c0b) | (r == c0c);
            const bool fc1 = (r == c1a) | (r == c1b) | (r == c1c);
            const bool fc2 = (r == c2a) | (r == c2b) | (r == c2c);
            const bool fc3 = (r == c3a) | (r == c3b) | (r == c3c);

            float4 so, co;
            comp1(v4.x, fr0, fc0, rm, sm0, so.x, co.x);
            comp1(v4.y, fr1, fc1, rm, sm1, so.y, co.y);
            comp1(v4.z, fr2, fc2, rm, sm2, so.z, co.z);
            comp1(v4.w, fr3, fc3, rm, sm3, so.w, co.w);

            *reinterpret_cast<float4*>(outs + off) = so;
            *reinterpret_cast<float4*>(outc + off) = co;
        }
    }
}

extern "C" void kernel_launch(void* const* d_in, const int* in_sizes, int n_in,
                              void* d_out, int out_size) {
    const float* score = (const float*)d_in[0];
    // d_in[1] = node_corr_scores (unused: conditional=False in reference)
    const int*   refm  = (const int*)d_in[2];   // bool -> int32 in harness
    const int*   srcm  = (const int*)d_in[3];   // bool -> int32 in harness
    float* out = (float*)d_out;

    const long long n_total = (long long)in_sizes[0];   // P*R*S
    const int P = (int)(n_total / (RR * SS));

    iapm_kernel<<<P, 256>>>(score, refm, srcm, out, n_total);
}